// round 6
// baseline (speedup 1.0000x reference)
#include <cuda_runtime.h>
#include <cuda_bf16.h>
#include <math.h>
#include <stdint.h>

#define NN 2048
#define DD 64
#define PP 32
#define NSTOP 512
#define KIN 4131          // original combined length
#define KP2 2112          // new GEMM K: 32 pref + 2048 dist + 3 scalars, padded
#define NC2 66            // KP2/32
#define BM 128
#define BN 128
#define NSTG 4
#define TILE_U32 2048     // 128x32 bf16 = 2048 uint32
#define STAGE_U32 4096
#define STAGE_B 16384
#define GEMM_SMEM (NSTG * STAGE_B)

// ---------------- scratch (device globals: allocation-free) ----------------
__device__ unsigned d_kmask[NN / 32];
__device__ int   d_klist[NSTOP];
__device__ __align__(16) float d_xn[NN * DD];
__device__ __align__(16) float d_xnc[NSTOP * DD];
__device__ __align__(16) float d_embc[NSTOP * DD];
__device__ __align__(16) float d_aggn[NN * DD];
__device__ float d_pref[NN * PP];
__device__ float d_av[NN];
__device__ float d_bv[NN];
// es analytic machinery
__device__ float d_bs[NN];          // sorted b
__device__ int   d_perm[NN];        // sort permutation
__device__ int   d_mrow[NN];        // suffix start per row i
__device__ float d_ap[NN];          // a'_i = a_i + edge_b
__device__ __align__(16) float d_w2t[(size_t)NN * NN];        // W2^T [j][r]
__device__ float d_B0[64 * NN], d_B1[64 * NN];                // chunk sums
__device__ float d_C0[65 * NN], d_C1[65 * NN];                // coarse suffix
__device__ __align__(16) float d_tt0[(size_t)(NN + 1) * NN];  // suffix sums [m][r]
__device__ __align__(16) float d_tt1[(size_t)(NN + 1) * NN];
// mma-fragment packed operands
__device__ __align__(128) uint32_t d_apack[(size_t)NN * KP2 / 2];
__device__ __align__(128) uint32_t d_bpack[(size_t)NN * KP2 / 2];

// ---------------- helpers ----------------
__device__ __forceinline__ uint32_t smem_u32(const void* p) {
    uint32_t a;
    asm("{ .reg .u64 t; cvta.to.shared.u64 t, %1; cvt.u32.u64 %0, t; }" : "=r"(a) : "l"(p));
    return a;
}
__device__ __forceinline__ uint32_t pack_bf16(float a, float b) {
    __nv_bfloat162 h = __floats2bfloat162_rn(a, b);
    return *(uint32_t*)&h;
}
#define CP_ASYNC16(dst, src) \
    asm volatile("cp.async.cg.shared.global [%0], [%1], 16;" :: "r"(dst), "l"(src) : "memory")
#define CP_COMMIT() asm volatile("cp.async.commit_group;" ::: "memory")
#define CP_WAIT(n)  asm volatile("cp.async.wait_group %0;" :: "n"(n) : "memory")

#define MMA16(c, a, b) \
    asm volatile("mma.sync.aligned.m16n8k16.row.col.f32.bf16.bf16.f32 " \
        "{%0,%1,%2,%3},{%4,%5,%6,%7},{%8,%9},{%0,%1,%2,%3};" \
        : "+f"((c)[0]), "+f"((c)[1]), "+f"((c)[2]), "+f"((c)[3]) \
        : "r"((a)[0]), "r"((a)[1]), "r"((a)[2]), "r"((a)[3]), \
          "r"((b)[0]), "r"((b)[1]))

__device__ __forceinline__ int keep_bit(int i) {
    return (d_kmask[i >> 5] >> (i & 31)) & 1;
}

// ---------------- init ----------------
__global__ void k_zero() {
    int i = blockIdx.x * blockDim.x + threadIdx.x;
    if (i < NN * DD) d_aggn[i] = 0.f;
    if (i < NN / 32) d_kmask[i] = 0u;
    if (i < NN) {                    // empty-suffix row m = NN
        d_tt0[(size_t)NN * NN + i] = 0.f;
        d_tt1[(size_t)NN * NN + i] = 0.f;
    }
}
__global__ void k_scatter(const int* __restrict__ stops) {
    int i = blockIdx.x * blockDim.x + threadIdx.x;
    if (i < NSTOP) {
        int s = stops[i];
        atomicOr(&d_kmask[s >> 5], 1u << (s & 31));
    }
}

// ---------------- row-normalize embeddings ----------------
__global__ void k_norm(const float* __restrict__ emb) {
    int i = blockIdx.x;
    int t = threadIdx.x;                 // 64
    float v = emb[i * DD + t];
    float s = v * v;
    #pragma unroll
    for (int o = 16; o; o >>= 1) s += __shfl_down_sync(0xffffffffu, s, o);
    __shared__ float ws[2];
    if ((t & 31) == 0) ws[t >> 5] = s;
    __syncthreads();
    float norm = fmaxf(sqrtf(ws[0] + ws[1]), 1e-8f);
    d_xn[i * DD + t] = v / norm;
}

// ---------------- deterministic compaction of kept rows ----------------
__global__ void k_compact(const float* __restrict__ emb) {   // grid NN, block 64
    int i = blockIdx.x, t = threadIdx.x;
    unsigned w = d_kmask[i >> 5];
    if (!((w >> (i & 31)) & 1)) return;
    __shared__ int spos;
    if (t == 0) {
        int pos = 0;
        for (int q = 0; q < (i >> 5); q++) pos += __popc(d_kmask[q]);
        pos += __popc(w & ((1u << (i & 31)) - 1u));
        spos = pos;
        d_klist[pos] = i;
    }
    __syncthreads();
    int pos = spos;
    d_xnc[pos * DD + t] = d_xn[i * DD + t];
    d_embc[pos * DD + t] = emb[i * DD + t];
}

// ---------------- agg over compacted kept set ----------------
__global__ void k_agg2() {                                   // grid NSTOP, block 256
    int b = blockIdx.x, t = threadIdx.x;
    __shared__ int snk;
    __shared__ __align__(16) float xi[DD];
    __shared__ unsigned mw[NSTOP / 32];
    __shared__ int degs;
    __shared__ float aggp[256];
    if (t == 0) { snk = 0; degs = 0; }
    if (t < NSTOP / 32) mw[t] = 0u;
    __syncthreads();
    if (t < NN / 32) atomicAdd(&snk, __popc(d_kmask[t]));
    __syncthreads();
    int nk = snk;
    if (b >= nk) return;
    if (t < DD) xi[t] = d_xnc[b * DD + t];
    __syncthreads();

    int cnt = 0;
    const float4* xi4 = (const float4*)xi;
    for (int j = t; j < nk; j += 256) {
        if (j == b) continue;
        const float4* xj = (const float4*)(d_xnc + j * DD);
        float s = 0.f;
        #pragma unroll
        for (int q = 0; q < DD / 4; q++) {
            float4 a = xj[q], bb = xi4[q];
            s += a.x * bb.x + a.y * bb.y + a.z * bb.z + a.w * bb.w;
        }
        if (s > 0.5f) { atomicOr(&mw[j >> 5], 1u << (j & 31)); cnt++; }
    }
    if (cnt) atomicAdd(&degs, cnt);
    __syncthreads();

    float deg = fmaxf((float)degs, 1.0f);
    int d = t & (DD - 1);
    int g = t >> 6;
    float p = 0.f;
    for (int j = g; j < nk; j += 4) {
        if ((mw[j >> 5] >> (j & 31)) & 1u) p += d_embc[j * DD + d];
    }
    aggp[t] = p;
    __syncthreads();
    if (t < DD) {
        float s = aggp[t] + aggp[t + 64] + aggp[t + 128] + aggp[t + 192];
        d_aggn[d_klist[b] * DD + t] = s / deg;
    }
}

// ---------------- pref + edge vectors ----------------
__global__ void k_pref(const float* __restrict__ emb,
                       const float* __restrict__ llw, const float* __restrict__ llb,
                       const float* __restrict__ lrw, const float* __restrict__ ew) {
    int i = blockIdx.x;
    int p = threadIdx.x;                 // 32
    float s = llb[p];
    const float* ai = d_aggn + i * DD;
    const float* ei = emb + i * DD;
    #pragma unroll
    for (int d = 0; d < DD; d++)
        s += ai[d] * llw[p * DD + d] + ei[d] * lrw[p * DD + d];
    d_pref[i * PP + p] = s;
    float a = s * ew[p];
    float b = s * ew[PP + p];
    #pragma unroll
    for (int o = 16; o; o >>= 1) {
        a += __shfl_down_sync(0xffffffffu, a, o);
        b += __shfl_down_sync(0xffffffffu, b, o);
    }
    if (p == 0) { d_av[i] = a; d_bv[i] = b; }
}

// ---------------- bitonic sort of b (ascending), single block ----------------
__global__ void k_sort() {
    __shared__ float key[NN];
    __shared__ int   val[NN];
    int t = threadIdx.x;                 // 1024
    for (int i = t; i < NN; i += 1024) { key[i] = d_bv[i]; val[i] = i; }
    __syncthreads();
    for (int k = 2; k <= NN; k <<= 1) {
        for (int j = k >> 1; j > 0; j >>= 1) {
            for (int i = t; i < NN; i += 1024) {
                int ixj = i ^ j;
                if (ixj > i) {
                    bool up = ((i & k) == 0);
                    float ki_ = key[i], kj_ = key[ixj];
                    bool sw = up ? (ki_ > kj_) : (ki_ < kj_);
                    if (sw) {
                        key[i] = kj_; key[ixj] = ki_;
                        int v = val[i]; val[i] = val[ixj]; val[ixj] = v;
                    }
                }
            }
            __syncthreads();
        }
    }
    for (int i = t; i < NN; i += 1024) { d_bs[i] = key[i]; d_perm[i] = val[i]; }
}

// ---------------- per-row suffix start (binary search) ----------------
__global__ void k_mrow(const float* __restrict__ edge_b) {   // grid 8, block 256
    int i = blockIdx.x * 256 + threadIdx.x;
    float ap = d_av[i] + edge_b[0];
    d_ap[i] = ap;
    float th = -ap;
    int lo = 0, hi = NN;
    while (lo < hi) {
        int mid = (lo + hi) >> 1;
        if (d_bs[mid] < th) lo = mid + 1; else hi = mid;
    }
    d_mrow[i] = lo;
}

// ---------------- W2 transpose: d_w2t[j][r] = combw[r][32+j] ----------------
__global__ void k_w2t(const float* __restrict__ combw) {     // grid (64,64), block(32,8)
    __shared__ float tile[32][33];
    int bx = blockIdx.x, by = blockIdx.y;
    int tx = threadIdx.x, ty = threadIdx.y;
    #pragma unroll
    for (int q = 0; q < 4; q++) {
        int r = by * 32 + ty + q * 8;
        tile[ty + q * 8][tx] = combw[(size_t)r * KIN + PP + bx * 32 + tx];
    }
    __syncthreads();
    #pragma unroll
    for (int q = 0; q < 4; q++) {
        int j = bx * 32 + ty + q * 8;
        d_w2t[(size_t)j * NN + by * 32 + tx] = tile[tx][ty + q * 8];
    }
}

// ---------------- chunk sums over sorted order ----------------
__global__ void k_coarse() {                                 // grid (64,8), block 256
    int g = blockIdx.x, r = blockIdx.y * 256 + threadIdx.x;
    __shared__ int sp[32];
    __shared__ float sb[32];
    if (threadIdx.x < 32) {
        sp[threadIdx.x] = d_perm[g * 32 + threadIdx.x];
        sb[threadIdx.x] = d_bs[g * 32 + threadIdx.x];
    }
    __syncthreads();
    float a0 = 0.f, a1 = 0.f;
    #pragma unroll 4
    for (int t = 0; t < 32; t++) {
        float w = d_w2t[(size_t)sp[t] * NN + r];
        a0 += w; a1 += sb[t] * w;
    }
    d_B0[g * NN + r] = a0;
    d_B1[g * NN + r] = a1;
}

// ---------------- coarse suffix scan over chunks ----------------
__global__ void k_cscan() {                                  // grid 8, block 256
    int r = blockIdx.x * 256 + threadIdx.x;
    float a0 = 0.f, a1 = 0.f;
    d_C0[64 * NN + r] = 0.f;
    d_C1[64 * NN + r] = 0.f;
    for (int g = 63; g >= 0; g--) {
        a0 += d_B0[g * NN + r];
        a1 += d_B1[g * NN + r];
        d_C0[g * NN + r] = a0;
        d_C1[g * NN + r] = a1;
    }
}

// ---------------- full suffix sums TT[m][r] ----------------
__global__ void k_tt() {                                     // grid (64,8), block 256
    int g = blockIdx.x, r = blockIdx.y * 256 + threadIdx.x;
    __shared__ int sp[32];
    __shared__ float sb[32];
    if (threadIdx.x < 32) {
        sp[threadIdx.x] = d_perm[g * 32 + threadIdx.x];
        sb[threadIdx.x] = d_bs[g * 32 + threadIdx.x];
    }
    __syncthreads();
    float a0 = d_C0[(g + 1) * NN + r];
    float a1 = d_C1[(g + 1) * NN + r];
    for (int t = 31; t >= 0; t--) {
        float w = d_w2t[(size_t)sp[t] * NN + r];
        a0 += w; a1 += sb[t] * w;
        int m = g * 32 + t;
        d_tt0[(size_t)m * NN + r] = a0;
        d_tt1[(size_t)m * NN + r] = a1;
    }
}

// ---------------- A operand value at (i,k) — new K layout ----------------
__device__ __forceinline__ float aval(int i, int k, const float* __restrict__ dist,
                                      float wkf, float vhf) {
    if (k < PP) return d_pref[i * PP + k];
    if (k < PP + NN) return dist[(size_t)i * NN + (k - PP)];
    if (k == PP + NN) return wkf;
    if (k == PP + NN + 1) return vhf;
    if (k == PP + NN + 2) return keep_bit(i) ? 1.f : 0.f;
    return 0.f;
}
// B operand: map new k -> original comb_w column (skip es block)
__device__ __forceinline__ float bval(int i, int k, const float* __restrict__ combw) {
    int c;
    if (k < PP) c = k;
    else if (k < PP + NN) c = k + NN;        // dist weights
    else if (k < PP + NN + 3) c = k + NN;    // 4128..4130 scalars
    else return 0.f;
    return combw[(size_t)i * KIN + c];
}

// A pack: m16n8k16 A-fragment order, bf16 pairs.
__global__ void k_fill_a(const float* __restrict__ dist,
                         const int* __restrict__ wk, const int* __restrict__ vh) {
    int idx = blockIdx.x * blockDim.x + threadIdx.x;
    if (idx >= NN * (KP2 / 2)) return;
    int i = idx / (KP2 / 2);
    int k = (idx - i * (KP2 / 2)) * 2;
    float wkf = (float)wk[0], vhf = (float)vh[0];
    float v0 = aval(i, k, dist, wkf, vhf);
    float v1 = aval(i, k + 1, dist, wkf, vhf);
    int mt = i >> 7, r = i & 127, kc = k >> 5, kk = k & 31;
    int ki = kk >> 4, kkk = kk & 15;
    int mi = r >> 4, rr = r & 15, g = rr & 7, hi = rr >> 3;
    int sel = kkk >> 3, tg = (kkk & 7) >> 1;
    int reg = sel * 2 + hi;
    int lane = g * 4 + tg;
    size_t off = (size_t)(mt * NC2 + kc) * TILE_U32 + (ki * 8 + mi) * 128 + lane * 4 + reg;
    d_apack[off] = pack_bf16(v0, v1);
}

// B pack: m16n8k16 B-fragment order, bf16 pairs.
__global__ void k_fill_b(const float* __restrict__ combw) {
    int idx = blockIdx.x * blockDim.x + threadIdx.x;
    if (idx >= NN * (KP2 / 2)) return;
    int i = idx / (KP2 / 2);
    int k = (idx - i * (KP2 / 2)) * 2;
    float v0 = bval(i, k, combw);
    float v1 = bval(i, k + 1, combw);
    int nt = i >> 7, r = i & 127, kc = k >> 5, kk = k & 31;
    int ki = kk >> 4, kkk = kk & 15;
    int ni = r >> 3, gb = r & 7;
    int reg = kkk >> 3, tg = (kkk & 7) >> 1;
    int lane = gb * 4 + tg;
    size_t off = (size_t)(nt * NC2 + kc) * TILE_U32 + (ki * 16 + ni) * 64 + lane * 2 + reg;
    d_bpack[off] = pack_bf16(v0, v1);
}

// ---------------- stage loader ----------------
__device__ __forceinline__ void load_stage(uint32_t sbase, int s,
                                           const uint32_t* aP, const uint32_t* bP, int tid) {
    uint32_t dst = sbase + s * STAGE_B + tid * 16;
    CP_ASYNC16(dst,          aP + tid * 4);
    CP_ASYNC16(dst + 4096,   aP + 1024 + tid * 4);
    CP_ASYNC16(dst + 8192,   bP + tid * 4);
    CP_ASYNC16(dst + 12288,  bP + 1024 + tid * 4);
}

// ---------------- bf16 mma GEMM + es-analytic epilogue ----------------
__global__ __launch_bounds__(256, 2) void k_gemm_mma(const float* __restrict__ bias,
                                                     float* __restrict__ C) {
    extern __shared__ __align__(16) uint32_t smu[];
    int tid = threadIdx.x, lane = tid & 31, wid = tid >> 5;
    int warpM = wid & 3, warpN = wid >> 2;      // 4 x 2
    int mt = blockIdx.y, nt = blockIdx.x;
    const uint32_t* aP0 = d_apack + (size_t)mt * NC2 * TILE_U32;
    const uint32_t* bP0 = d_bpack + (size_t)nt * NC2 * TILE_U32;
    uint32_t sbase = smem_u32(smu);

    float acc[2][8][4];
    #pragma unroll
    for (int m = 0; m < 2; m++)
        #pragma unroll
        for (int n = 0; n < 8; n++)
            #pragma unroll
            for (int q = 0; q < 4; q++) acc[m][n][q] = 0.f;

    #pragma unroll
    for (int p = 0; p < NSTG - 1; p++) {
        load_stage(sbase, p, aP0 + (size_t)p * TILE_U32, bP0 + (size_t)p * TILE_U32, tid);
        CP_COMMIT();
    }

    for (int kc = 0; kc < NC2; kc++) {
        CP_WAIT(NSTG - 2);
        __syncthreads();
        int pf = kc + NSTG - 1;
        if (pf < NC2)
            load_stage(sbase, pf % NSTG, aP0 + (size_t)pf * TILE_U32,
                       bP0 + (size_t)pf * TILE_U32, tid);
        CP_COMMIT();

        const uint32_t* As = smu + (kc % NSTG) * STAGE_U32;
        const uint32_t* Bs = As + TILE_U32;
        #pragma unroll
        for (int ki = 0; ki < 2; ki++) {
            uint32_t af[2][4];
            #pragma unroll
            for (int m = 0; m < 2; m++) {
                uint4 v = *(const uint4*)(As + ((ki * 8 + warpM * 2 + m) * 128 + lane * 4));
                af[m][0] = v.x; af[m][1] = v.y; af[m][2] = v.z; af[m][3] = v.w;
            }
            uint32_t bf[8][2];
            #pragma unroll
            for (int n = 0; n < 8; n++) {
                uint2 w = *(const uint2*)(Bs + ((ki * 16 + warpN * 8 + n) * 64 + lane * 2));
                bf[n][0] = w.x; bf[n][1] = w.y;
            }
            #pragma unroll
            for (int m = 0; m < 2; m++)
                #pragma unroll
                for (int n = 0; n < 8; n++) MMA16(acc[m][n], af[m], bf[n]);
        }
    }

    // epilogue: += bias + 0.01(a' T0 + T1)[full] + 0.99(a' TT0[m_i] + TT1[m_i])
    int g = lane >> 2, tg = lane & 3;
    int rowBase = mt * BM + warpM * 32;
    int colBase = nt * BN + warpN * 64;
    int rA0 = rowBase + g,      rA1 = rA0 + 8;       // m=0 fragment rows
    int rB0 = rowBase + 16 + g, rB1 = rB0 + 8;       // m=1 fragment rows
    float ap0 = d_ap[rA0], ap1 = d_ap[rA1], ap2 = d_ap[rB0], ap3 = d_ap[rB1];
    const float* t00 = d_tt0 + (size_t)d_mrow[rA0] * NN;
    const float* t01 = d_tt1 + (size_t)d_mrow[rA0] * NN;
    const float* t10 = d_tt0 + (size_t)d_mrow[rA1] * NN;
    const float* t11 = d_tt1 + (size_t)d_mrow[rA1] * NN;
    const float* t20 = d_tt0 + (size_t)d_mrow[rB0] * NN;
    const float* t21 = d_tt1 + (size_t)d_mrow[rB0] * NN;
    const float* t30 = d_tt0 + (size_t)d_mrow[rB1] * NN;
    const float* t31 = d_tt1 + (size_t)d_mrow[rB1] * NN;

    #pragma unroll
    for (int n = 0; n < 8; n++) {
        int c = colBase + n * 8 + tg * 2;
        float2 bb = *(const float2*)(bias + c);
        float2 z0 = *(const float2*)(d_tt0 + c);     // m=0 full sums
        float2 z1 = *(const float2*)(d_tt1 + c);
        float basex = bb.x + 0.01f * z1.x;
        float basey = bb.y + 0.01f * z1.y;

        float2 sA0 = *(const float2*)(t00 + c), sA1 = *(const float2*)(t01 + c);
        float2 sB0 = *(const float2*)(t10 + c), sB1 = *(const float2*)(t11 + c);
        float2 sC0 = *(const float2*)(t20 + c), sC1 = *(const float2*)(t21 + c);
        float2 sD0 = *(const float2*)(t30 + c), sD1 = *(const float2*)(t31 + c);

        float2 o;
        o.x = acc[0][n][0] + basex + 0.01f * ap0 * z0.x + 0.99f * (ap0 * sA0.x + sA1.x);
        o.y = acc[0][n][1] + basey + 0.01f * ap0 * z0.y + 0.99f * (ap0 * sA0.y + sA1.y);
        *(float2*)(C + (size_t)rA0 * NN + c) = o;
        o.x = acc[0][n][2] + basex + 0.01f * ap1 * z0.x + 0.99f * (ap1 * sB0.x + sB1.x);
        o.y = acc[0][n][3] + basey + 0.01f * ap1 * z0.y + 0.99f * (ap1 * sB0.y + sB1.y);
        *(float2*)(C + (size_t)rA1 * NN + c) = o;
        o.x = acc[1][n][0] + basex + 0.01f * ap2 * z0.x + 0.99f * (ap2 * sC0.x + sC1.x);
        o.y = acc[1][n][1] + basey + 0.01f * ap2 * z0.y + 0.99f * (ap2 * sC0.y + sC1.y);
        *(float2*)(C + (size_t)rB0 * NN + c) = o;
        o.x = acc[1][n][2] + basex + 0.01f * ap3 * z0.x + 0.99f * (ap3 * sD0.x + sD1.x);
        o.y = acc[1][n][3] + basey + 0.01f * ap3 * z0.y + 0.99f * (ap3 * sD0.y + sD1.y);
        *(float2*)(C + (size_t)rB1 * NN + c) = o;
    }
}

// ---------------- in-place row log-softmax ----------------
__global__ void k_lsm(float* __restrict__ out) {
    int i = blockIdx.x;
    int t = threadIdx.x;                 // 256
    __shared__ float row[NN];
    __shared__ float red[256];

    float m = -1e30f;
    for (int j = t; j < NN; j += 256) {
        float v = out[(size_t)i * NN + j];
        row[j] = v;
        m = fmaxf(m, v);
    }
    red[t] = m;
    __syncthreads();
    #pragma unroll
    for (int o = 128; o; o >>= 1) {
        if (t < o) red[t] = fmaxf(red[t], red[t + o]);
        __syncthreads();
    }
    float mx = red[0];
    __syncthreads();

    float s = 0.f;
    for (int j = t; j < NN; j += 256) s += __expf(row[j] - mx);
    red[t] = s;
    __syncthreads();
    #pragma unroll
    for (int o = 128; o; o >>= 1) {
        if (t < o) red[t] += red[t + o];
        __syncthreads();
    }
    float lse = logf(red[0]) + mx;

    for (int j = t; j < NN; j += 256) out[(size_t)i * NN + j] = row[j] - lse;
}

// ---------------- launch ----------------
extern "C" void kernel_launch(void* const* d_in, const int* in_sizes, int n_in,
                              void* d_out, int out_size) {
    const float* dist   = (const float*)d_in[0];
    const float* emb    = (const float*)d_in[1];
    const float* llw    = (const float*)d_in[2];
    const float* llb    = (const float*)d_in[3];
    const float* lrw    = (const float*)d_in[4];
    const float* ew     = (const float*)d_in[5];
    const float* edge_b = (const float*)d_in[6];
    const float* combw  = (const float*)d_in[7];
    const float* combb  = (const float*)d_in[8];
    const int*   stops  = (const int*)d_in[9];
    const int*   wk     = (const int*)d_in[10];
    const int*   vh     = (const int*)d_in[11];
    float* out = (float*)d_out;

    k_zero<<<(NN * DD + 255) / 256, 256>>>();
    k_scatter<<<(NSTOP + 255) / 256, 256>>>(stops);
    k_norm<<<NN, DD>>>(emb);
    k_compact<<<NN, DD>>>(emb);
    k_agg2<<<NSTOP, 256>>>();
    k_pref<<<NN, PP>>>(emb, llw, llb, lrw, ew);

    // es-analytic machinery
    k_sort<<<1, 1024>>>();
    k_mrow<<<NN / 256, 256>>>(edge_b);
    dim3 tg(64, 64);
    k_w2t<<<tg, dim3(32, 8)>>>(combw);
    k_coarse<<<dim3(64, NN / 256), 256>>>();
    k_cscan<<<NN / 256, 256>>>();
    k_tt<<<dim3(64, NN / 256), 256>>>();

    int tot = NN * (KP2 / 2);
    k_fill_a<<<(tot + 255) / 256, 256>>>(dist, wk, vh);
    k_fill_b<<<(tot + 255) / 256, 256>>>(combw);

    cudaFuncSetAttribute(k_gemm_mma, cudaFuncAttributeMaxDynamicSharedMemorySize, GEMM_SMEM);
    dim3 gg(NN / BN, NN / BM);
    k_gemm_mma<<<gg, 256, GEMM_SMEM>>>(combb, out);

    k_lsm<<<NN, 256>>>(out);
}

// round 7
// speedup vs baseline: 1.2128x; 1.2128x over previous
#include <cuda_runtime.h>
#include <cuda_bf16.h>
#include <math.h>
#include <stdint.h>

#define NN 2048
#define DD 64
#define PP 32
#define NSTOP 512
#define KIN 4131          // 2*N + 3 + P
#define KPAD 4160         // 130 chunks of 32
#define NCHUNK 130
#define BM 128
#define BN 128
#define NSTG 4
#define TILE_U32 2048     // 128x32 bf16 = 2048 uint32 = 8KB
#define STAGE_U32 4096
#define STAGE_B 16384
#define GEMM_SMEM (NSTG * STAGE_B)

// ---------------- scratch (device globals: allocation-free) ----------------
__device__ unsigned d_kmask[NN / 32];
__device__ int   d_klist[NSTOP];
__device__ __align__(16) float d_xn[NN * DD];
__device__ __align__(16) float d_xnc[NSTOP * DD];
__device__ __align__(16) float d_embc[NSTOP * DD];
__device__ __align__(16) float d_aggn[NN * DD];
__device__ float d_pref[NN * PP];
__device__ float d_av[NN];
__device__ float d_bv[NN];
// m16n8k16 bf16 fragment-packed operands
__device__ __align__(128) uint32_t d_apack[(size_t)NN * KPAD / 2];
__device__ __align__(128) uint32_t d_bpack[(size_t)NN * KPAD / 2];

// ---------------- helpers ----------------
__device__ __forceinline__ uint32_t smem_u32(const void* p) {
    uint32_t a;
    asm("{ .reg .u64 t; cvta.to.shared.u64 t, %1; cvt.u32.u64 %0, t; }" : "=r"(a) : "l"(p));
    return a;
}
__device__ __forceinline__ uint32_t pack_bf16(float a, float b) {
    __nv_bfloat162 h = __floats2bfloat162_rn(a, b);
    return *(uint32_t*)&h;
}
#define CP_ASYNC16(dst, src) \
    asm volatile("cp.async.cg.shared.global [%0], [%1], 16;" :: "r"(dst), "l"(src) : "memory")
#define CP_COMMIT() asm volatile("cp.async.commit_group;" ::: "memory")
#define CP_WAIT(n)  asm volatile("cp.async.wait_group %0;" :: "n"(n) : "memory")

#define MMA16(c, a, b) \
    asm volatile("mma.sync.aligned.m16n8k16.row.col.f32.bf16.bf16.f32 " \
        "{%0,%1,%2,%3},{%4,%5,%6,%7},{%8,%9},{%0,%1,%2,%3};" \
        : "+f"((c)[0]), "+f"((c)[1]), "+f"((c)[2]), "+f"((c)[3]) \
        : "r"((a)[0]), "r"((a)[1]), "r"((a)[2]), "r"((a)[3]), \
          "r"((b)[0]), "r"((b)[1]))

__device__ __forceinline__ int keep_bit(int i) {
    return (d_kmask[i >> 5] >> (i & 31)) & 1;
}

// ---------------- init: zero mask + zero agg + row-normalize ----------------
__global__ void k_init(const float* __restrict__ emb) {      // grid NN, block 64
    int i = blockIdx.x;
    int t = threadIdx.x;
    d_aggn[i * DD + t] = 0.f;
    if (t == 0 && i < NN / 32) d_kmask[i] = 0u;

    float v = emb[i * DD + t];
    float s = v * v;
    #pragma unroll
    for (int o = 16; o; o >>= 1) s += __shfl_down_sync(0xffffffffu, s, o);
    __shared__ float ws[2];
    if ((t & 31) == 0) ws[t >> 5] = s;
    __syncthreads();
    float norm = fmaxf(sqrtf(ws[0] + ws[1]), 1e-8f);
    d_xn[i * DD + t] = v / norm;
}
__global__ void k_scatter(const int* __restrict__ stops) {
    int i = blockIdx.x * blockDim.x + threadIdx.x;
    if (i < NSTOP) {
        int s = stops[i];
        atomicOr(&d_kmask[s >> 5], 1u << (s & 31));
    }
}

// ---------------- deterministic compaction of kept rows ----------------
__global__ void k_compact(const float* __restrict__ emb) {   // grid NN, block 64
    int i = blockIdx.x, t = threadIdx.x;
    unsigned w = d_kmask[i >> 5];
    if (!((w >> (i & 31)) & 1)) return;
    __shared__ int spos;
    if (t == 0) {
        int pos = 0;
        for (int q = 0; q < (i >> 5); q++) pos += __popc(d_kmask[q]);
        pos += __popc(w & ((1u << (i & 31)) - 1u));
        spos = pos;
        d_klist[pos] = i;
    }
    __syncthreads();
    int pos = spos;
    d_xnc[pos * DD + t] = d_xn[i * DD + t];
    d_embc[pos * DD + t] = emb[i * DD + t];
}

// ---------------- agg over compacted kept set ----------------
__global__ void k_agg2() {                                   // grid NSTOP, block 256
    int b = blockIdx.x, t = threadIdx.x;
    __shared__ int snk;
    __shared__ __align__(16) float xi[DD];
    __shared__ unsigned mw[NSTOP / 32];
    __shared__ int degs;
    __shared__ float aggp[256];
    if (t == 0) { snk = 0; degs = 0; }
    if (t < NSTOP / 32) mw[t] = 0u;
    __syncthreads();
    if (t < NN / 32) atomicAdd(&snk, __popc(d_kmask[t]));
    __syncthreads();
    int nk = snk;
    if (b >= nk) return;
    if (t < DD) xi[t] = d_xnc[b * DD + t];
    __syncthreads();

    int cnt = 0;
    const float4* xi4 = (const float4*)xi;
    for (int j = t; j < nk; j += 256) {
        if (j == b) continue;
        const float4* xj = (const float4*)(d_xnc + j * DD);
        float s = 0.f;
        #pragma unroll
        for (int q = 0; q < DD / 4; q++) {
            float4 a = xj[q], bb = xi4[q];
            s += a.x * bb.x + a.y * bb.y + a.z * bb.z + a.w * bb.w;
        }
        if (s > 0.5f) { atomicOr(&mw[j >> 5], 1u << (j & 31)); cnt++; }
    }
    if (cnt) atomicAdd(&degs, cnt);
    __syncthreads();

    float deg = fmaxf((float)degs, 1.0f);
    int d = t & (DD - 1);
    int g = t >> 6;
    float p = 0.f;
    for (int j = g; j < nk; j += 4) {
        if ((mw[j >> 5] >> (j & 31)) & 1u) p += d_embc[j * DD + d];
    }
    aggp[t] = p;
    __syncthreads();
    if (t < DD) {
        float s = aggp[t] + aggp[t + 64] + aggp[t + 128] + aggp[t + 192];
        d_aggn[d_klist[b] * DD + t] = s / deg;
    }
}

// ---------------- pref + edge vectors (8 rows/block) ----------------
__global__ void k_pref(const float* __restrict__ emb,
                       const float* __restrict__ llw, const float* __restrict__ llb,
                       const float* __restrict__ lrw, const float* __restrict__ ew) {
    int i = blockIdx.x * 8 + (threadIdx.x >> 5);
    int p = threadIdx.x & 31;
    float s = llb[p];
    const float* ai = d_aggn + i * DD;
    const float* ei = emb + i * DD;
    #pragma unroll
    for (int d = 0; d < DD; d++)
        s += ai[d] * llw[p * DD + d] + ei[d] * lrw[p * DD + d];
    d_pref[i * PP + p] = s;
    float a = s * ew[p];
    float b = s * ew[PP + p];
    #pragma unroll
    for (int o = 16; o; o >>= 1) {
        a += __shfl_down_sync(0xffffffffu, a, o);
        b += __shfl_down_sync(0xffffffffu, b, o);
    }
    if (p == 0) { d_av[i] = a; d_bv[i] = b; }
}

// ---------------- combined value at (i,k) ----------------
__device__ __forceinline__ float comb_val(int i, int k, const float* __restrict__ dist,
                                          float eb, float wkf, float vhf) {
    if (k < PP) return d_pref[i * PP + k];
    if (k < PP + NN) {
        float e = d_av[i] + d_bv[k - PP] + eb;
        return (e >= 0.f) ? e : 0.01f * e;
    }
    if (k < PP + 2 * NN) return dist[(size_t)i * NN + (k - PP - NN)];
    if (k == PP + 2 * NN) return wkf;
    if (k == PP + 2 * NN + 1) return vhf;
    if (k == PP + 2 * NN + 2) return keep_bit(i) ? 1.f : 0.f;
    return 0.f;
}

// ---------------- A fill: iterate over fragment offsets, coalesced uint4 stores --
// layout: off = (ki*8+mi)*128 + lane*4 + reg; lane=g*4+tg; reg=sel*2+hi;
// row=mi*16+hi*8+g; kk=ki*16+sel*8+tg*2(+b)
__global__ void k_fill_a(const float* __restrict__ dist, const float* __restrict__ edge_b,
                         const int* __restrict__ wk, const int* __restrict__ vh) {
    int kc = blockIdx.x, mt = blockIdx.y;
    int t = threadIdx.x;                 // 512
    int lane = t & 31, fragq = t >> 5;   // fragq 0..15
    int ki = fragq >> 3, mi = fragq & 7;
    int g = lane >> 2, tg = lane & 3;
    int i0 = mt * 128 + mi * 16 + g;
    int i1 = i0 + 8;
    int kA = kc * 32 + ki * 16 + tg * 2;
    int kB = kA + 8;
    float eb = edge_b[0], wkf = (float)wk[0], vhf = (float)vh[0];
    uint4 v;
    v.x = pack_bf16(comb_val(i0, kA, dist, eb, wkf, vhf), comb_val(i0, kA + 1, dist, eb, wkf, vhf));
    v.y = pack_bf16(comb_val(i1, kA, dist, eb, wkf, vhf), comb_val(i1, kA + 1, dist, eb, wkf, vhf));
    v.z = pack_bf16(comb_val(i0, kB, dist, eb, wkf, vhf), comb_val(i0, kB + 1, dist, eb, wkf, vhf));
    v.w = pack_bf16(comb_val(i1, kB, dist, eb, wkf, vhf), comb_val(i1, kB + 1, dist, eb, wkf, vhf));
    *(uint4*)(d_apack + (size_t)(mt * NCHUNK + kc) * TILE_U32 + fragq * 128 + lane * 4) = v;
}

// ---------------- B fill: fragment-offset iteration, coalesced uint2 stores -----
// layout: off = (ki*16+ni)*64 + lane*2 + reg; lane=gb*4+tg; row=ni*8+gb;
// kk=ki*16+reg*8+tg*2(+b)
__global__ void k_fill_b(const float* __restrict__ combw) {
    int kc = blockIdx.x, nt = blockIdx.y;
    int t = threadIdx.x;                 // 1024
    int lane = t & 31, fragq = t >> 5;   // fragq 0..31
    int ki = fragq >> 4, ni = fragq & 15;
    int gb = lane >> 2, tg = lane & 3;
    int i = nt * 128 + ni * 8 + gb;      // weight row = output column
    int k0 = kc * 32 + ki * 16 + tg * 2;
    int k1 = k0 + 8;
    const float* wrow = combw + (size_t)i * KIN;
    float a0 = (k0     < KIN) ? wrow[k0]     : 0.f;
    float a1 = (k0 + 1 < KIN) ? wrow[k0 + 1] : 0.f;
    float b0 = (k1     < KIN) ? wrow[k1]     : 0.f;
    float b1 = (k1 + 1 < KIN) ? wrow[k1 + 1] : 0.f;
    uint2 v;
    v.x = pack_bf16(a0, a1);
    v.y = pack_bf16(b0, b1);
    *(uint2*)(d_bpack + (size_t)(nt * NCHUNK + kc) * TILE_U32 + fragq * 64 + lane * 2) = v;
}

// ---------------- stage loader: 16KB, 128 threads ----------------
__device__ __forceinline__ void load_stage(uint32_t sbase, int s,
                                           const uint32_t* aP, const uint32_t* bP, int tid) {
    uint32_t dst = sbase + s * STAGE_B + tid * 16;
    #pragma unroll
    for (int j = 0; j < 4; j++) CP_ASYNC16(dst + j * 2048, aP + tid * 4 + j * 512);
    dst += 8192;
    #pragma unroll
    for (int j = 0; j < 4; j++) CP_ASYNC16(dst + j * 2048, bP + tid * 4 + j * 512);
}

// ---------------- bf16 mma GEMM: C[128x128] per CTA, 4 warps 64x64 each --------
__global__ __launch_bounds__(128, 2) void k_gemm_mma(const float* __restrict__ bias,
                                                     float* __restrict__ C) {
    extern __shared__ __align__(16) uint32_t smu[];
    int tid = threadIdx.x, lane = tid & 31, wid = tid >> 5;
    int warpM = wid & 1, warpN = wid >> 1;      // 2 x 2 warps, 64x64 each
    int mt = blockIdx.y, nt = blockIdx.x;
    const uint32_t* aP0 = d_apack + (size_t)mt * NCHUNK * TILE_U32;
    const uint32_t* bP0 = d_bpack + (size_t)nt * NCHUNK * TILE_U32;
    uint32_t sbase = smem_u32(smu);

    float acc[4][8][4];
    #pragma unroll
    for (int m = 0; m < 4; m++)
        #pragma unroll
        for (int n = 0; n < 8; n++)
            #pragma unroll
            for (int q = 0; q < 4; q++) acc[m][n][q] = 0.f;

    #pragma unroll
    for (int p = 0; p < NSTG - 1; p++) {
        load_stage(sbase, p, aP0 + (size_t)p * TILE_U32, bP0 + (size_t)p * TILE_U32, tid);
        CP_COMMIT();
    }

    for (int kc = 0; kc < NCHUNK; kc++) {
        CP_WAIT(NSTG - 2);
        __syncthreads();
        int pf = kc + NSTG - 1;
        if (pf < NCHUNK)
            load_stage(sbase, pf % NSTG, aP0 + (size_t)pf * TILE_U32,
                       bP0 + (size_t)pf * TILE_U32, tid);
        CP_COMMIT();

        const uint32_t* As = smu + (kc % NSTG) * STAGE_U32;
        const uint32_t* Bs = As + TILE_U32;
        #pragma unroll
        for (int ki = 0; ki < 2; ki++) {
            uint32_t af[4][4];
            #pragma unroll
            for (int m = 0; m < 4; m++) {
                uint4 v = *(const uint4*)(As + ((ki * 8 + warpM * 4 + m) * 128 + lane * 4));
                af[m][0] = v.x; af[m][1] = v.y; af[m][2] = v.z; af[m][3] = v.w;
            }
            uint32_t bf[8][2];
            #pragma unroll
            for (int n = 0; n < 8; n++) {
                uint2 w = *(const uint2*)(Bs + ((ki * 16 + warpN * 8 + n) * 64 + lane * 2));
                bf[n][0] = w.x; bf[n][1] = w.y;
            }
            #pragma unroll
            for (int m = 0; m < 4; m++)
                #pragma unroll
                for (int n = 0; n < 8; n++) MMA16(acc[m][n], af[m], bf[n]);
        }
    }

    // epilogue
    int g = lane >> 2, tg = lane & 3;
    int rowBase = mt * BM + warpM * 64;
    int colBase = nt * BN + warpN * 64;
    #pragma unroll
    for (int m = 0; m < 4; m++) {
        int r0 = rowBase + m * 16 + g;
        #pragma unroll
        for (int n = 0; n < 8; n++) {
            int c = colBase + n * 8 + tg * 2;
            float2 bb = *(const float2*)(bias + c);
            float2 o0 = { acc[m][n][0] + bb.x, acc[m][n][1] + bb.y };
            float2 o1 = { acc[m][n][2] + bb.x, acc[m][n][3] + bb.y };
            *(float2*)(C + (size_t)r0 * NN + c) = o0;
            *(float2*)(C + (size_t)(r0 + 8) * NN + c) = o1;
        }
    }
}

// ---------------- in-place row log-softmax ----------------
__global__ void k_lsm(float* __restrict__ out) {
    int i = blockIdx.x;
    int t = threadIdx.x;                 // 256
    __shared__ float row[NN];
    __shared__ float red[256];

    float m = -1e30f;
    for (int j = t; j < NN; j += 256) {
        float v = out[(size_t)i * NN + j];
        row[j] = v;
        m = fmaxf(m, v);
    }
    red[t] = m;
    __syncthreads();
    #pragma unroll
    for (int o = 128; o; o >>= 1) {
        if (t < o) red[t] = fmaxf(red[t], red[t + o]);
        __syncthreads();
    }
    float mx = red[0];
    __syncthreads();

    float s = 0.f;
    for (int j = t; j < NN; j += 256) s += __expf(row[j] - mx);
    red[t] = s;
    __syncthreads();
    #pragma unroll
    for (int o = 128; o; o >>= 1) {
        if (t < o) red[t] += red[t + o];
        __syncthreads();
    }
    float lse = logf(red[0]) + mx;

    for (int j = t; j < NN; j += 256) out[(size_t)i * NN + j] = row[j] - lse;
}

// ---------------- launch ----------------
extern "C" void kernel_launch(void* const* d_in, const int* in_sizes, int n_in,
                              void* d_out, int out_size) {
    const float* dist   = (const float*)d_in[0];
    const float* emb    = (const float*)d_in[1];
    const float* llw    = (const float*)d_in[2];
    const float* llb    = (const float*)d_in[3];
    const float* lrw    = (const float*)d_in[4];
    const float* ew     = (const float*)d_in[5];
    const float* edge_b = (const float*)d_in[6];
    const float* combw  = (const float*)d_in[7];
    const float* combb  = (const float*)d_in[8];
    const int*   stops  = (const int*)d_in[9];
    const int*   wk     = (const int*)d_in[10];
    const int*   vh     = (const int*)d_in[11];
    float* out = (float*)d_out;

    k_init<<<NN, DD>>>(emb);
    k_scatter<<<(NSTOP + 255) / 256, 256>>>(stops);
    k_compact<<<NN, DD>>>(emb);
    k_agg2<<<NSTOP, 256>>>();
    k_pref<<<NN / 8, 256>>>(emb, llw, llb, lrw, ew);

    dim3 fg(NCHUNK, 16);
    k_fill_a<<<fg, 512>>>(dist, edge_b, wk, vh);
    k_fill_b<<<fg, 1024>>>(combw);

    cudaFuncSetAttribute(k_gemm_mma, cudaFuncAttributeMaxDynamicSharedMemorySize, GEMM_SMEM);
    dim3 gg(NN / BN, NN / BM);
    k_gemm_mma<<<gg, 128, GEMM_SMEM>>>(combb, out);

    k_lsm<<<NN, 256>>>(out);
}

// round 8
// speedup vs baseline: 1.2932x; 1.0663x over previous
#include <cuda_runtime.h>
#include <cuda_bf16.h>
#include <math.h>
#include <stdint.h>

#define NN 2048
#define DD 64
#define PP 32
#define NSTOP 512
#define KIN 4131          // 2*N + 3 + P
#define KPAD 4160         // 130 chunks of 32
#define NCHUNK 130
#define BM 128
#define BN 128
#define NSTG 4
#define TILE_U32 2048     // 128x32 bf16 = 2048 uint32 = 8KB
#define STAGE_U32 4096
#define STAGE_B 16384
#define GEMM_SMEM (NSTG * STAGE_B)

// ---------------- scratch (device globals: allocation-free) ----------------
__device__ unsigned d_kmask[NN / 32];
__device__ int   d_klist[NSTOP];
__device__ int   d_nk;
__device__ __align__(16) float d_xn[NN * DD];
__device__ __align__(16) float d_xnc[NSTOP * DD];
__device__ __align__(16) float d_embc[NSTOP * DD];
__device__ __align__(16) float d_aggn[NN * DD];
__device__ __align__(16) float d_aggs[4 * NSTOP * DD];   // per-slice partial sums
__device__ int   d_degp[4 * NSTOP];                      // per-slice partial degrees
__device__ float d_pref[NN * PP];
__device__ float d_av[NN];
__device__ float d_bv[NN];
// m16n8k16 bf16 fragment-packed operands
__device__ __align__(128) uint32_t d_apack[(size_t)NN * KPAD / 2];
__device__ __align__(128) uint32_t d_bpack[(size_t)NN * KPAD / 2];

// ---------------- helpers ----------------
__device__ __forceinline__ uint32_t smem_u32(const void* p) {
    uint32_t a;
    asm("{ .reg .u64 t; cvta.to.shared.u64 t, %1; cvt.u32.u64 %0, t; }" : "=r"(a) : "l"(p));
    return a;
}
__device__ __forceinline__ uint32_t pack_bf16(float a, float b) {
    __nv_bfloat162 h = __floats2bfloat162_rn(a, b);
    return *(uint32_t*)&h;
}
#define CP_ASYNC16(dst, src) \
    asm volatile("cp.async.cg.shared.global [%0], [%1], 16;" :: "r"(dst), "l"(src) : "memory")
#define CP_COMMIT() asm volatile("cp.async.commit_group;" ::: "memory")
#define CP_WAIT(n)  asm volatile("cp.async.wait_group %0;" :: "n"(n) : "memory")

#define MMA16(c, a, b) \
    asm volatile("mma.sync.aligned.m16n8k16.row.col.f32.bf16.bf16.f32 " \
        "{%0,%1,%2,%3},{%4,%5,%6,%7},{%8,%9},{%0,%1,%2,%3};" \
        : "+f"((c)[0]), "+f"((c)[1]), "+f"((c)[2]), "+f"((c)[3]) \
        : "r"((a)[0]), "r"((a)[1]), "r"((a)[2]), "r"((a)[3]), \
          "r"((b)[0]), "r"((b)[1]))

__device__ __forceinline__ int keep_bit(int i) {
    return (d_kmask[i >> 5] >> (i & 31)) & 1;
}

// ---------------- init: zero everything + row-normalize ----------------
__global__ void k_init(const float* __restrict__ emb) {      // grid NN, block 64
    int i = blockIdx.x;
    int t = threadIdx.x;
    int idx = i * DD + t;
    d_aggn[idx] = 0.f;
    d_aggs[idx] = 0.f;           // 4*NSTOP*DD == NN*DD
    if (idx < 4 * NSTOP) d_degp[idx] = 0;
    if (idx < NN / 32) d_kmask[idx] = 0u;
    if (idx == 0) d_nk = 0;

    float v = emb[idx];
    float s = v * v;
    #pragma unroll
    for (int o = 16; o; o >>= 1) s += __shfl_down_sync(0xffffffffu, s, o);
    __shared__ float ws[2];
    if ((t & 31) == 0) ws[t >> 5] = s;
    __syncthreads();
    float norm = fmaxf(sqrtf(ws[0] + ws[1]), 1e-8f);
    d_xn[idx] = v / norm;
}
__global__ void k_scatter(const int* __restrict__ stops) {
    int i = blockIdx.x * blockDim.x + threadIdx.x;
    if (i < NSTOP) {
        int s = stops[i];
        atomicOr(&d_kmask[s >> 5], 1u << (s & 31));
    }
}

// ---------------- deterministic compaction of kept rows ----------------
__global__ void k_compact(const float* __restrict__ emb) {   // grid NN, block 64
    int i = blockIdx.x, t = threadIdx.x;
    unsigned w = d_kmask[i >> 5];
    if (!((w >> (i & 31)) & 1)) return;
    __shared__ int spos;
    if (t == 0) {
        int pos = 0;
        for (int q = 0; q < (i >> 5); q++) pos += __popc(d_kmask[q]);
        pos += __popc(w & ((1u << (i & 31)) - 1u));
        spos = pos;
        d_klist[pos] = i;
        atomicMax(&d_nk, pos + 1);
    }
    __syncthreads();
    int pos = spos;
    d_xnc[pos * DD + t] = d_xn[i * DD + t];
    d_embc[pos * DD + t] = emb[i * DD + t];
}

// ---------------- agg phase A: per-slice partials, grid (NSTOP,4), block 128 ----
__global__ void k_agg2p() {
    int b = blockIdx.x, y = blockIdx.y, t = threadIdx.x;
    int nk = d_nk;
    if (b >= nk) return;
    __shared__ __align__(16) float xi[DD];
    __shared__ unsigned mw[4];
    __shared__ float aggp[128];
    if (t < DD) xi[t] = d_xnc[b * DD + t];
    __syncthreads();

    int wid = t >> 5, lane = t & 31;
    int j = y * 128 + wid * 32 + lane;
    bool pred = false;
    if (j < nk && j != b) {
        const float4* xj = (const float4*)(d_xnc + j * DD);
        const float4* xi4 = (const float4*)xi;
        float s = 0.f;
        #pragma unroll
        for (int q = 0; q < DD / 4; q++) {
            float4 a = xj[q], bb = xi4[q];
            s += a.x * bb.x + a.y * bb.y + a.z * bb.z + a.w * bb.w;
        }
        pred = (s > 0.5f);
    }
    unsigned m = __ballot_sync(0xffffffffu, pred);
    if (lane == 0) mw[wid] = m;
    __syncthreads();

    int cnt = __popc(mw[0]) + __popc(mw[1]) + __popc(mw[2]) + __popc(mw[3]);
    if (cnt == 0) return;              // slots pre-zeroed in k_init
    if (t == 0) d_degp[y * NSTOP + b] = cnt;

    int d = t & 63, half = t >> 6;
    float p = 0.f;
    #pragma unroll
    for (int w = half * 2; w < half * 2 + 2; w++) {
        unsigned mm = mw[w];
        while (mm) {
            int bit = __ffs(mm) - 1;
            mm &= mm - 1;
            p += d_embc[(y * 128 + w * 32 + bit) * DD + d];
        }
    }
    aggp[t] = p;
    __syncthreads();
    if (t < DD) d_aggs[(y * NSTOP + b) * DD + t] = aggp[t] + aggp[t + 64];
}

// ---------------- agg phase B: combine slices + divide ----------------
__global__ void k_aggdiv() {                                 // grid NSTOP, block 64
    int b = blockIdx.x, t = threadIdx.x;
    if (b >= d_nk) return;
    int deg = d_degp[b] + d_degp[NSTOP + b] + d_degp[2 * NSTOP + b] + d_degp[3 * NSTOP + b];
    float dg = fmaxf((float)deg, 1.0f);
    float s = d_aggs[b * DD + t] + d_aggs[(NSTOP + b) * DD + t]
            + d_aggs[(2 * NSTOP + b) * DD + t] + d_aggs[(3 * NSTOP + b) * DD + t];
    d_aggn[d_klist[b] * DD + t] = s / dg;
}

// ---------------- pref + edge vectors (8 rows/block) ----------------
__global__ void k_pref(const float* __restrict__ emb,
                       const float* __restrict__ llw, const float* __restrict__ llb,
                       const float* __restrict__ lrw, const float* __restrict__ ew) {
    int i = blockIdx.x * 8 + (threadIdx.x >> 5);
    int p = threadIdx.x & 31;
    float s = llb[p];
    const float* ai = d_aggn + i * DD;
    const float* ei = emb + i * DD;
    #pragma unroll
    for (int d = 0; d < DD; d++)
        s += ai[d] * llw[p * DD + d] + ei[d] * lrw[p * DD + d];
    d_pref[i * PP + p] = s;
    float a = s * ew[p];
    float b = s * ew[PP + p];
    #pragma unroll
    for (int o = 16; o; o >>= 1) {
        a += __shfl_down_sync(0xffffffffu, a, o);
        b += __shfl_down_sync(0xffffffffu, b, o);
    }
    if (p == 0) { d_av[i] = a; d_bv[i] = b; }
}

// ---------------- combined value at (i,k) ----------------
__device__ __forceinline__ float comb_val(int i, int k, const float* __restrict__ dist,
                                          float eb, float wkf, float vhf) {
    if (k < PP) return d_pref[i * PP + k];
    if (k < PP + NN) {
        float e = d_av[i] + d_bv[k - PP] + eb;
        return (e >= 0.f) ? e : 0.01f * e;
    }
    if (k < PP + 2 * NN) return dist[(size_t)i * NN + (k - PP - NN)];
    if (k == PP + 2 * NN) return wkf;
    if (k == PP + 2 * NN + 1) return vhf;
    if (k == PP + 2 * NN + 2) return keep_bit(i) ? 1.f : 0.f;
    return 0.f;
}

// ---------------- A fill: fragment-offset iteration, coalesced uint4 stores ----
__global__ void k_fill_a(const float* __restrict__ dist, const float* __restrict__ edge_b,
                         const int* __restrict__ wk, const int* __restrict__ vh) {
    int kc = blockIdx.x, mt = blockIdx.y;
    int t = threadIdx.x;                 // 512
    int lane = t & 31, fragq = t >> 5;   // fragq 0..15
    int ki = fragq >> 3, mi = fragq & 7;
    int g = lane >> 2, tg = lane & 3;
    int i0 = mt * 128 + mi * 16 + g;
    int i1 = i0 + 8;
    int kA = kc * 32 + ki * 16 + tg * 2;
    int kB = kA + 8;
    float eb = edge_b[0], wkf = (float)wk[0], vhf = (float)vh[0];
    uint4 v;
    v.x = pack_bf16(comb_val(i0, kA, dist, eb, wkf, vhf), comb_val(i0, kA + 1, dist, eb, wkf, vhf));
    v.y = pack_bf16(comb_val(i1, kA, dist, eb, wkf, vhf), comb_val(i1, kA + 1, dist, eb, wkf, vhf));
    v.z = pack_bf16(comb_val(i0, kB, dist, eb, wkf, vhf), comb_val(i0, kB + 1, dist, eb, wkf, vhf));
    v.w = pack_bf16(comb_val(i1, kB, dist, eb, wkf, vhf), comb_val(i1, kB + 1, dist, eb, wkf, vhf));
    *(uint4*)(d_apack + (size_t)(mt * NCHUNK + kc) * TILE_U32 + fragq * 128 + lane * 4) = v;
}

// ---------------- B fill: fragment-offset iteration, coalesced uint2 stores ----
__global__ void k_fill_b(const float* __restrict__ combw) {
    int kc = blockIdx.x, nt = blockIdx.y;
    int t = threadIdx.x;                 // 1024
    int lane = t & 31, fragq = t >> 5;   // fragq 0..31
    int ki = fragq >> 4, ni = fragq & 15;
    int gb = lane >> 2, tg = lane & 3;
    int i = nt * 128 + ni * 8 + gb;      // weight row = output column
    int k0 = kc * 32 + ki * 16 + tg * 2;
    int k1 = k0 + 8;
    const float* wrow = combw + (size_t)i * KIN;
    float a0 = (k0     < KIN) ? wrow[k0]     : 0.f;
    float a1 = (k0 + 1 < KIN) ? wrow[k0 + 1] : 0.f;
    float b0 = (k1     < KIN) ? wrow[k1]     : 0.f;
    float b1 = (k1 + 1 < KIN) ? wrow[k1 + 1] : 0.f;
    uint2 v;
    v.x = pack_bf16(a0, a1);
    v.y = pack_bf16(b0, b1);
    *(uint2*)(d_bpack + (size_t)(nt * NCHUNK + kc) * TILE_U32 + fragq * 64 + lane * 2) = v;
}

// ---------------- stage loader: 16KB, 128 threads ----------------
__device__ __forceinline__ void load_stage(uint32_t sbase, int s,
                                           const uint32_t* aP, const uint32_t* bP, int tid) {
    uint32_t dst = sbase + s * STAGE_B + tid * 16;
    #pragma unroll
    for (int j = 0; j < 4; j++) CP_ASYNC16(dst + j * 2048, aP + tid * 4 + j * 512);
    dst += 8192;
    #pragma unroll
    for (int j = 0; j < 4; j++) CP_ASYNC16(dst + j * 2048, bP + tid * 4 + j * 512);
}

// ---------------- bf16 mma GEMM: C[128x128] per CTA, 4 warps 64x64 each --------
__global__ __launch_bounds__(128, 2) void k_gemm_mma(const float* __restrict__ bias,
                                                     float* __restrict__ C) {
    extern __shared__ __align__(16) uint32_t smu[];
    int tid = threadIdx.x, lane = tid & 31, wid = tid >> 5;
    int warpM = wid & 1, warpN = wid >> 1;      // 2 x 2 warps, 64x64 each
    int mt = blockIdx.y, nt = blockIdx.x;
    const uint32_t* aP0 = d_apack + (size_t)mt * NCHUNK * TILE_U32;
    const uint32_t* bP0 = d_bpack + (size_t)nt * NCHUNK * TILE_U32;
    uint32_t sbase = smem_u32(smu);

    float acc[4][8][4];
    #pragma unroll
    for (int m = 0; m < 4; m++)
        #pragma unroll
        for (int n = 0; n < 8; n++)
            #pragma unroll
            for (int q = 0; q < 4; q++) acc[m][n][q] = 0.f;

    #pragma unroll
    for (int p = 0; p < NSTG - 1; p++) {
        load_stage(sbase, p, aP0 + (size_t)p * TILE_U32, bP0 + (size_t)p * TILE_U32, tid);
        CP_COMMIT();
    }

    for (int kc = 0; kc < NCHUNK; kc++) {
        CP_WAIT(NSTG - 2);
        __syncthreads();
        int pf = kc + NSTG - 1;
        if (pf < NCHUNK)
            load_stage(sbase, pf % NSTG, aP0 + (size_t)pf * TILE_U32,
                       bP0 + (size_t)pf * TILE_U32, tid);
        CP_COMMIT();

        const uint32_t* As = smu + (kc % NSTG) * STAGE_U32;
        const uint32_t* Bs = As + TILE_U32;
        #pragma unroll
        for (int ki = 0; ki < 2; ki++) {
            uint32_t af[4][4];
            #pragma unroll
            for (int m = 0; m < 4; m++) {
                uint4 v = *(const uint4*)(As + ((ki * 8 + warpM * 4 + m) * 128 + lane * 4));
                af[m][0] = v.x; af[m][1] = v.y; af[m][2] = v.z; af[m][3] = v.w;
            }
            uint32_t bf[8][2];
            #pragma unroll
            for (int n = 0; n < 8; n++) {
                uint2 w = *(const uint2*)(Bs + ((ki * 16 + warpN * 8 + n) * 64 + lane * 2));
                bf[n][0] = w.x; bf[n][1] = w.y;
            }
            #pragma unroll
            for (int m = 0; m < 4; m++)
                #pragma unroll
                for (int n = 0; n < 8; n++) MMA16(acc[m][n], af[m], bf[n]);
        }
    }

    // epilogue
    int g = lane >> 2, tg = lane & 3;
    int rowBase = mt * BM + warpM * 64;
    int colBase = nt * BN + warpN * 64;
    #pragma unroll
    for (int m = 0; m < 4; m++) {
        int r0 = rowBase + m * 16 + g;
        #pragma unroll
        for (int n = 0; n < 8; n++) {
            int c = colBase + n * 8 + tg * 2;
            float2 bb = *(const float2*)(bias + c);
            float2 o0 = { acc[m][n][0] + bb.x, acc[m][n][1] + bb.y };
            float2 o1 = { acc[m][n][2] + bb.x, acc[m][n][3] + bb.y };
            *(float2*)(C + (size_t)r0 * NN + c) = o0;
            *(float2*)(C + (size_t)(r0 + 8) * NN + c) = o1;
        }
    }
}

// ---------------- register-resident row log-softmax ----------------
__global__ void k_lsm(float* __restrict__ out) {
    int i = blockIdx.x;
    int t = threadIdx.x;                 // 256
    int lane = t & 31, wid = t >> 5;
    float4* rp = (float4*)(out + (size_t)i * NN);
    float4 v0 = rp[t];
    float4 v1 = rp[t + 256];

    float m = fmaxf(fmaxf(fmaxf(v0.x, v0.y), fmaxf(v0.z, v0.w)),
                    fmaxf(fmaxf(v1.x, v1.y), fmaxf(v1.z, v1.w)));
    #pragma unroll
    for (int o = 16; o; o >>= 1) m = fmaxf(m, __shfl_xor_sync(0xffffffffu, m, o));
    __shared__ float sA[8];
    __shared__ float sbc;
    if (lane == 0) sA[wid] = m;
    __syncthreads();
    if (t == 0) {
        float mm = sA[0];
        #pragma unroll
        for (int w = 1; w < 8; w++) mm = fmaxf(mm, sA[w]);
        sbc = mm;
    }
    __syncthreads();
    float mx = sbc;

    float s = __expf(v0.x - mx) + __expf(v0.y - mx) + __expf(v0.z - mx) + __expf(v0.w - mx)
            + __expf(v1.x - mx) + __expf(v1.y - mx) + __expf(v1.z - mx) + __expf(v1.w - mx);
    #pragma unroll
    for (int o = 16; o; o >>= 1) s += __shfl_xor_sync(0xffffffffu, s, o);
    __syncthreads();                     // protect sA before rewrite
    if (lane == 0) sA[wid] = s;
    __syncthreads();
    if (t == 0) {
        float ss = 0.f;
        #pragma unroll
        for (int w = 0; w < 8; w++) ss += sA[w];
        sbc = logf(ss) + mx;
    }
    __syncthreads();
    float lse = sbc;

    v0.x -= lse; v0.y -= lse; v0.z -= lse; v0.w -= lse;
    v1.x -= lse; v1.y -= lse; v1.z -= lse; v1.w -= lse;
    rp[t] = v0;
    rp[t + 256] = v1;
}

// ---------------- launch ----------------
extern "C" void kernel_launch(void* const* d_in, const int* in_sizes, int n_in,
                              void* d_out, int out_size) {
    const float* dist   = (const float*)d_in[0];
    const float* emb    = (const float*)d_in[1];
    const float* llw    = (const float*)d_in[2];
    const float* llb    = (const float*)d_in[3];
    const float* lrw    = (const float*)d_in[4];
    const float* ew     = (const float*)d_in[5];
    const float* edge_b = (const float*)d_in[6];
    const float* combw  = (const float*)d_in[7];
    const float* combb  = (const float*)d_in[8];
    const int*   stops  = (const int*)d_in[9];
    const int*   wk     = (const int*)d_in[10];
    const int*   vh     = (const int*)d_in[11];
    float* out = (float*)d_out;

    k_init<<<NN, DD>>>(emb);
    k_scatter<<<(NSTOP + 255) / 256, 256>>>(stops);
    k_compact<<<NN, DD>>>(emb);
    k_agg2p<<<dim3(NSTOP, 4), 128>>>();
    k_aggdiv<<<NSTOP, DD>>>();
    k_pref<<<NN / 8, 256>>>(emb, llw, llb, lrw, ew);

    dim3 fg(NCHUNK, 16);
    k_fill_a<<<fg, 512>>>(dist, edge_b, wk, vh);
    k_fill_b<<<fg, 1024>>>(combw);

    cudaFuncSetAttribute(k_gemm_mma, cudaFuncAttributeMaxDynamicSharedMemorySize, GEMM_SMEM);
    dim3 gg(NN / BN, NN / BM);
    k_gemm_mma<<<gg, 128, GEMM_SMEM>>>(combb, out);

    k_lsm<<<NN, 256>>>(out);
}